// round 1
// baseline (speedup 1.0000x reference)
#include <cuda_runtime.h>

// Shapes (fixed): B=8, H=8, N=2048, C=64  -> BH=64 head-batches
#define NTOK 2048
#define CDIM 64
#define NBH  64

// Scratch (alloc-free rule: __device__ globals). 3 x 33.5 MB.
__device__ float g_q[NBH * NTOK * CDIM];
__device__ float g_k[NBH * NTOK * CDIM];
__device__ float g_v[NBH * NTOK * CDIM];

typedef unsigned long long u64;

__device__ __forceinline__ u64 pk2(float lo, float hi) {
    u64 r; asm("mov.b64 %0,{%1,%2};" : "=l"(r) : "f"(lo), "f"(hi)); return r;
}
__device__ __forceinline__ void up2(u64 v, float &lo, float &hi) {
    asm("mov.b64 {%0,%1},%2;" : "=f"(lo), "=f"(hi) : "l"(v));
}
__device__ __forceinline__ u64 f2fma(u64 a, u64 b, u64 c) {
    u64 d; asm("fma.rn.f32x2 %0,%1,%2,%3;" : "=l"(d) : "l"(a), "l"(b), "l"(c)); return d;
}
__device__ __forceinline__ u64 f2mul(u64 a, u64 b) {
    u64 d; asm("mul.rn.f32x2 %0,%1,%2;" : "=l"(d) : "l"(a), "l"(b)); return d;
}

// ---------------------------------------------------------------------------
// Kernel 1: fused QKV projection.  qkv[row, d] = sum_c x[row, c] * W[d, c]
// rows = BH*N = 131072, W is [192, 64]. W staged in smem (48 KB), x row in regs.
// ---------------------------------------------------------------------------
__global__ void __launch_bounds__(256) qkv_kernel(const float* __restrict__ x,
                                                  const float* __restrict__ W) {
    extern __shared__ float Ws[];  // 192*64 floats = 49152 B
    for (int i = threadIdx.x; i < 192 * 64; i += 256) Ws[i] = W[i];
    __syncthreads();

    int row = blockIdx.x * 256 + threadIdx.x;  // 0 .. 131071
    float xr[64];
    const float4* xp = (const float4*)(x + (size_t)row * 64);
#pragma unroll
    for (int c4 = 0; c4 < 16; c4++) {
        float4 t = xp[c4];
        xr[c4 * 4 + 0] = t.x; xr[c4 * 4 + 1] = t.y;
        xr[c4 * 4 + 2] = t.z; xr[c4 * 4 + 3] = t.w;
    }

    for (int d = 0; d < 192; d += 4) {
        float a0 = 0.f, a1 = 0.f, a2 = 0.f, a3 = 0.f;
        const float* w0 = &Ws[d * 64];
#pragma unroll
        for (int c = 0; c < 64; c++) {
            float xv = xr[c];
            a0 = fmaf(xv, w0[c],        a0);
            a1 = fmaf(xv, w0[64 + c],   a1);
            a2 = fmaf(xv, w0[128 + c],  a2);
            a3 = fmaf(xv, w0[192 + c],  a3);
        }
        float* dst = (d < 64) ? g_q : ((d < 128) ? g_k : g_v);
        int dd = d & 63;
        *(float4*)&dst[(size_t)row * 64 + dd] = make_float4(a0, a1, a2, a3);
    }
}

// ---------------------------------------------------------------------------
// Kernel 2: flash attention per (b,h) + fused head-mixing shuffle.
// BM=BN=64, 256 threads as 16x16, each thread owns a 4x4 microtile.
// Both GEMMs run on packed fma.rn.f32x2 (FFMA2).
// ---------------------------------------------------------------------------
#define BM 64
#define BN 64
#define QS_OFF 0
#define KT_OFF (64 * 65)                 // Qs stride 65 (scalar col access)
#define VS_OFF (KT_OFF + 64 * 68)        // KT stride 68 (16B-aligned row access)
#define PS_OFF (VS_OFF + 64 * 64)        // Vs stride 64
#define SMEM_FLOATS (PS_OFF + 64 * 64)   // Ps stride 64
#define SMEM_BYTES  (SMEM_FLOATS * 4)    // 66816 B

__global__ void __launch_bounds__(256) attn_kernel(float* __restrict__ out) {
    extern __shared__ float sm[];
    float* Qs = sm + QS_OFF;
    float* KT = sm + KT_OFF;
    float* Vs = sm + VS_OFF;
    float* Ps = sm + PS_OFF;

    const int bh = blockIdx.y;
    const int m0 = blockIdx.x * BM;
    const float* qg = g_q + (size_t)bh * NTOK * CDIM;
    const float* kg = g_k + (size_t)bh * NTOK * CDIM;
    const float* vg = g_v + (size_t)bh * NTOK * CDIM;

    const int tid = threadIdx.x;
    const int ty = tid >> 4, tx = tid & 15;

    // Load Q tile (pre-scaled by 1/sqrt(C) = 0.125)
    for (int idx = tid; idx < BM * 64; idx += 256) {
        int r = idx >> 6, c = idx & 63;
        Qs[r * 65 + c] = qg[(m0 + r) * 64 + c] * 0.125f;
    }

    u64 o01[4], o23[4];
    float mi[4], li[4];
#pragma unroll
    for (int i = 0; i < 4; i++) { o01[i] = 0ull; o23[i] = 0ull; mi[i] = -1e30f; li[i] = 0.f; }

    for (int kt = 0; kt < NTOK / BN; kt++) {
        const int k0 = kt * BN;
        __syncthreads();   // previous PV reads done before overwriting KT/Vs
        for (int idx = tid; idx < BN * 64; idx += 256) {
            int r = idx >> 6, c = idx & 63;
            KT[c * 68 + r] = kg[(k0 + r) * 64 + c];   // transposed
            Vs[idx]        = vg[(k0 + r) * 64 + c];
        }
        __syncthreads();

        // ---- S = Q K^T (packed f32x2) ----
        u64 s01[4], s23[4];
#pragma unroll
        for (int i = 0; i < 4; i++) { s01[i] = 0ull; s23[i] = 0ull; }
        const float* qrow = &Qs[ty * 4 * 65];
        const float* ktc  = &KT[tx * 4];
#pragma unroll 4
        for (int c = 0; c < 64; c++) {
            u64 kk01 = *(const u64*)&ktc[c * 68];
            u64 kk23 = *(const u64*)&ktc[c * 68 + 2];
#pragma unroll
            for (int i = 0; i < 4; i++) {
                float qv = qrow[i * 65 + c];
                u64 qb = pk2(qv, qv);
                s01[i] = f2fma(qb, kk01, s01[i]);
                s23[i] = f2fma(qb, kk23, s23[i]);
            }
        }

        float s[4][4];
#pragma unroll
        for (int i = 0; i < 4; i++) { up2(s01[i], s[i][0], s[i][1]); up2(s23[i], s[i][2], s[i][3]); }

        // ---- online softmax (row reductions across 16 lanes) ----
        float alpha[4];
#pragma unroll
        for (int i = 0; i < 4; i++) {
            float m = fmaxf(fmaxf(s[i][0], s[i][1]), fmaxf(s[i][2], s[i][3]));
#pragma unroll
            for (int off = 8; off > 0; off >>= 1)
                m = fmaxf(m, __shfl_xor_sync(0xffffffffu, m, off));
            float mn = fmaxf(mi[i], m);
            alpha[i] = __expf(mi[i] - mn);
            mi[i] = mn;
            float r = 0.f;
#pragma unroll
            for (int j = 0; j < 4; j++) { s[i][j] = __expf(s[i][j] - mn); r += s[i][j]; }
#pragma unroll
            for (int off = 8; off > 0; off >>= 1)
                r += __shfl_xor_sync(0xffffffffu, r, off);
            li[i] = li[i] * alpha[i] + r;
        }

        // rescale O, publish P
#pragma unroll
        for (int i = 0; i < 4; i++) {
            u64 ab = pk2(alpha[i], alpha[i]);
            o01[i] = f2mul(o01[i], ab);
            o23[i] = f2mul(o23[i], ab);
            *(float4*)&Ps[(ty * 4 + i) * 64 + tx * 4] =
                make_float4(s[i][0], s[i][1], s[i][2], s[i][3]);
        }
        __syncthreads();

        // ---- O += P V (packed f32x2) ----
        const float* prow = &Ps[ty * 4 * 64];
        const float* vrow = &Vs[tx * 4];
#pragma unroll 4
        for (int k = 0; k < BN; k++) {
            u64 vv01 = *(const u64*)&vrow[k * 64];
            u64 vv23 = *(const u64*)&vrow[k * 64 + 2];
#pragma unroll
            for (int i = 0; i < 4; i++) {
                float pv = prow[i * 64 + k];
                u64 pb = pk2(pv, pv);
                o01[i] = f2fma(pb, vv01, o01[i]);
                o23[i] = f2fma(pb, vv23, o23[i]);
            }
        }
    }

    // ---- epilogue: normalize + head-mixing shuffle ----
    // final[b, h', n, h*8 + j'] = attn_out[b, h, n, h'*8 + j']
    const int b = bh >> 3, h = bh & 7;
#pragma unroll
    for (int i = 0; i < 4; i++) {
        float inv = 1.0f / li[i];
        int n = m0 + ty * 4 + i;
        float ov[4];
        up2(o01[i], ov[0], ov[1]); up2(o23[i], ov[2], ov[3]);
#pragma unroll
        for (int j = 0; j < 4; j++) {
            int cc = tx * 4 + j;
            int hp = cc >> 3, jp = cc & 7;
            out[(((b * 8 + hp) * NTOK + n) << 6) + h * 8 + jp] = ov[j] * inv;
        }
    }
}

// ---------------------------------------------------------------------------
extern "C" void kernel_launch(void* const* d_in, const int* in_sizes, int n_in,
                              void* d_out, int out_size) {
    const float* x = (const float*)d_in[0];      // [8,8,2048,64]
    const float* W = (const float*)d_in[1];      // [192,64]
    float* out = (float*)d_out;                  // [8,8,2048,64]

    cudaFuncSetAttribute(qkv_kernel,  cudaFuncAttributeMaxDynamicSharedMemorySize, 49152);
    cudaFuncSetAttribute(attn_kernel, cudaFuncAttributeMaxDynamicSharedMemorySize, SMEM_BYTES);

    qkv_kernel<<<(NBH * NTOK) / 256, 256, 49152>>>(x, W);
    attn_kernel<<<dim3(NTOK / BM, NBH), 256, SMEM_BYTES>>>(out);
}